// round 13
// baseline (speedup 1.0000x reference)
#include <cuda_runtime.h>
#include <cuda_fp16.h>
#include <cstdint>

#define NPTS 50000
#define DIM 256

// ---------------- scratch (no-alloc rule: __device__ globals) --------------
__device__ __half g_resh[NPTS * DIM];       // residual, half
__device__ __half g_a0h[NPTS * (DIM / 4)];  // init MLP out, half
__device__ __half g_a1h[NPTS * (DIM / 2)];  // LFA1 out, half
__device__ __half g_a2g[NPTS * (DIM / 2)];  // LFA2 geom half [N,128]
__device__ __half g_wcat[(DIM + DIM / 4) * DIM]; // [w_res^T ; w_init^T] [320,256]
__device__ __half g_wfT[DIM * DIM];         // w_fin^T half [256,256]

__device__ __forceinline__ float leaky(float x) {
    return x >= 0.0f ? x : 0.2f * x;
}

#define MMA_F16(c, a, b0, b1)                                             \
    asm volatile(                                                         \
        "mma.sync.aligned.m16n8k16.row.col.f32.f16.f16.f32 "              \
        "{%0,%1,%2,%3}, {%4,%5,%6,%7}, {%8,%9}, {%0,%1,%2,%3};"           \
        : "+f"((c)[0]), "+f"((c)[1]), "+f"((c)[2]), "+f"((c)[3])          \
        : "r"((a)[0]), "r"((a)[1]), "r"((a)[2]), "r"((a)[3]),             \
          "r"(b0), "r"(b1))

#define LDSM_X4(r0, r1, r2, r3, addr)                                     \
    asm volatile(                                                         \
        "ldmatrix.sync.aligned.m8n8.x4.shared.b16 {%0,%1,%2,%3}, [%4];"   \
        : "=r"(r0), "=r"(r1), "=r"(r2), "=r"(r3) : "r"(addr))

__device__ __forceinline__ void cp_async16(uint32_t dst, const void* src,
                                           uint32_t src_bytes) {
    asm volatile("cp.async.ca.shared.global [%0], [%1], 16, %2;"
                 :: "r"(dst), "l"(src), "r"(src_bytes));
}
#define CP_COMMIT() asm volatile("cp.async.commit_group;")
#define CP_WAIT(n)  asm volatile("cp.async.wait_group %0;" :: "n"(n))

__device__ __forceinline__ __half2 u2h2(uint32_t u) {
    return *reinterpret_cast<__half2*>(&u);
}

// ---------------------------------------------------------------------------
// prep_w: fp32 [K,N] -> half [N,K] for the three GEMM weights (144 blocks).
// ---------------------------------------------------------------------------
__global__ __launch_bounds__(256)
void prep_w(const float* __restrict__ w_res,
            const float* __restrict__ w_init,
            const float* __restrict__ w_fin,
            __half* __restrict__ wcat, __half* __restrict__ wfT)
{
    __shared__ float t[32][33];
    const int tid = threadIdx.x;
    const float* in;
    __half* out;
    int K = 256, Nc, bx;
    if (blockIdx.x < 64)      { in = w_res;  out = wcat; Nc = 256; bx = blockIdx.x; }
    else if (blockIdx.x < 80) { in = w_init; out = wcat + 256 * 256; Nc = 64;
                                bx = blockIdx.x - 64; }
    else                      { in = w_fin;  out = wfT;  Nc = 256; bx = blockIdx.x - 80; }
    int tx = tid & 31, ty = tid >> 5;
    int nTx = Nc / 32;
    int n0 = (bx % nTx) * 32;
    int k0 = (bx / nTx) * 32;
    for (int i = ty; i < 32; i += 8)
        t[i][tx] = in[(size_t)(k0 + i) * Nc + n0 + tx];
    __syncthreads();
    for (int i = ty; i < 32; i += 8)
        out[(size_t)(n0 + i) * K + k0 + tx] = __float2half(t[tx][i]);
}

// ---------------------------------------------------------------------------
// CAT GEMM (fused stage 1+2): CTA tile 64 x 320, grid.y = 1 — single X pass.
// ---------------------------------------------------------------------------
__global__ __launch_bounds__(256, 2)
void hgemm_cat(const float* __restrict__ A, const __half* __restrict__ Bt,
               const float* __restrict__ bias0, const float* __restrict__ bias1,
               __half* __restrict__ resh, __half* __restrict__ a0h, int M)
{
    constexpr int KD    = 256;
    constexpr int BK    = 64;
    constexpr int NST   = KD / BK;           // 4
    constexpr int CTAM  = 64;
    constexpr int CTAN  = 320;
    constexpr int ABY   = CTAM * 128;        // 8 KB
    constexpr int BBY   = CTAN * 128;        // 40 KB
    constexpr int STAGE = ABY + BBY;         // 48 KB
    constexpr int NT16  = CTAN / 32;         // 10
    constexpr int NT8   = 2 * NT16;          // 20

    extern __shared__ char smem[];
    const uint32_t sbase = (uint32_t)__cvta_generic_to_shared(smem);

    const int tid  = threadIdx.x;
    const int wid  = tid >> 5;
    const int lane = tid & 31;
    const int g = lane >> 2;
    const int l = lane & 3;
    const int quad = lane >> 3;
    const int lrow = lane & 7;
    const int warp_m = (wid & 3) * 16;
    const int warp_n = (wid >> 2) * (CTAN / 2);
    const int rowbase = blockIdx.x * CTAM;

    const int pa_r = tid >> 3, pa_c = tid & 7;

    const int arow  = warp_m + (quad & 1) * 8 + lrow;
    const int ac_hi = quad >> 1;
    const int brow0 = warp_n + ((quad >> 1) & 1) * 8 + lrow;
    const int bc_lo = quad & 1;

    float c[NT8][4];
    #pragma unroll
    for (int ni = 0; ni < NT8; ni++)
        #pragma unroll
        for (int j = 0; j < 4; j++)
            c[ni][j] = 0.0f;

    float4 aR[2][2];

    auto ldgA = [&](int t) {
        const int kk = t * BK;
        #pragma unroll
        for (int i = 0; i < 2; i++) {
            int hc = tid + i * 256;
            int r = hc >> 3, c8 = hc & 7;
            int grow = rowbase + r;
            if (grow < M) {
                const float4* src = reinterpret_cast<const float4*>(
                    A + (size_t)grow * KD + kk + c8 * 8);
                aR[i][0] = src[0];
                aR[i][1] = src[1];
            } else {
                aR[i][0] = make_float4(0.f, 0.f, 0.f, 0.f);
                aR[i][1] = make_float4(0.f, 0.f, 0.f, 0.f);
            }
        }
    };

    auto storeA = [&](int t) {
        char* st = smem + (t & 1) * STAGE;
        #pragma unroll
        for (int i = 0; i < 2; i++) {
            int hc = tid + i * 256;
            int r = hc >> 3, c8 = hc & 7;
            __half2 h0 = __float22half2_rn(make_float2(aR[i][0].x, aR[i][0].y));
            __half2 h1 = __float22half2_rn(make_float2(aR[i][0].z, aR[i][0].w));
            __half2 h2 = __float22half2_rn(make_float2(aR[i][1].x, aR[i][1].y));
            __half2 h3 = __float22half2_rn(make_float2(aR[i][1].z, aR[i][1].w));
            uint4 v;
            v.x = *reinterpret_cast<uint32_t*>(&h0);
            v.y = *reinterpret_cast<uint32_t*>(&h1);
            v.z = *reinterpret_cast<uint32_t*>(&h2);
            v.w = *reinterpret_cast<uint32_t*>(&h3);
            *reinterpret_cast<uint4*>(
                st + r * 128 + ((c8 ^ (r & 7)) << 4)) = v;
        }
    };

    auto issueB = [&](int t) {
        const int kk = t * BK;
        const uint32_t st = sbase + (t & 1) * STAGE;
        #pragma unroll
        for (int i = 0; i < 10; i++) {
            int r = pa_r + i * 32;
            const __half* src =
                Bt + (size_t)r * KD + kk + pa_c * 8;
            uint32_t dst = st + ABY + r * 128 + ((pa_c ^ (r & 7)) << 4);
            cp_async16(dst, src, 16u);
        }
        CP_COMMIT();
    };

    ldgA(0);
    issueB(0);
    issueB(1);
    storeA(0);
    CP_WAIT(1);
    __syncthreads();

    for (int t = 0; t < NST; t++) {
        const uint32_t st = sbase + (t & 1) * STAGE;
        if (t + 1 < NST) ldgA(t + 1);

        #pragma unroll
        for (int ks8 = 0; ks8 < BK / 8; ks8 += 2) {
            uint32_t af[4];
            {
                int cch = ks8 + ac_hi;
                uint32_t addr = st + arow * 128 + ((cch ^ (arow & 7)) << 4);
                LDSM_X4(af[0], af[1], af[2], af[3], addr);
            }
            #pragma unroll
            for (int nt = 0; nt < NT16; nt++) {
                uint32_t bf[4];
                int r = brow0 + nt * 16;
                int cch = ks8 + bc_lo;
                uint32_t addr = st + ABY + r * 128 + ((cch ^ (r & 7)) << 4);
                LDSM_X4(bf[0], bf[1], bf[2], bf[3], addr);
                MMA_F16(c[nt * 2 + 0], af, bf[0], bf[1]);
                MMA_F16(c[nt * 2 + 1], af, bf[2], bf[3]);
            }
        }
        __syncthreads();
        if (t + 1 < NST) {
            storeA(t + 1);
            if (t + 2 < NST) { issueB(t + 2); CP_WAIT(1); }
            else             { CP_WAIT(0); }
            __syncthreads();
        }
    }

    #pragma unroll
    for (int ni = 0; ni < NT8; ni++) {
        const int col = warp_n + ni * 8 + 2 * l;
        const bool isInit = (col >= 256);
        const float b0 = isInit ? bias1[col - 256] : bias0[col];
        const float b1 = isInit ? bias1[col - 255] : bias0[col + 1];
        #pragma unroll
        for (int hm = 0; hm < 2; hm++) {
            const int r = rowbase + warp_m + g + hm * 8;
            if (r >= M) continue;
            float ox = leaky(c[ni][hm * 2 + 0] + b0);
            float oy = leaky(c[ni][hm * 2 + 1] + b1);
            __half2 h = __float22half2_rn(make_float2(ox, oy));
            if (isInit)
                *reinterpret_cast<uint32_t*>(
                    a0h + (size_t)r * 64 + col - 256) =
                    *reinterpret_cast<uint32_t*>(&h);
            else
                *reinterpret_cast<uint32_t*>(
                    resh + (size_t)r * 256 + col) =
                    *reinterpret_cast<uint32_t*>(&h);
        }
    }
}

// ---------------------------------------------------------------------------
// geo_g1: merged launch, interleaved tasks per blockIdx parity.
//   task 0 (even): gather1  — a1h[p,64:128] = mean_k a0h[idx[p,k], :]
//   task 1 (odd):  geom MLP — a1h[p,0:64], a2g[p,0:128]
// ---------------------------------------------------------------------------
__global__ __launch_bounds__(256)
void geo_g1(const float* __restrict__ geom,
            const float* __restrict__ wg1, const float* __restrict__ bg1,
            const float* __restrict__ wg2, const float* __restrict__ bg2,
            const __half* __restrict__ a0h, const int* __restrict__ idx,
            __half* __restrict__ a1h, __half* __restrict__ a2g, int N)
{
    __shared__ int   is[32][16];
    __shared__ uint2 gsm[32][16];

    const int task = blockIdx.x & 1;
    const int bid  = blockIdx.x >> 1;
    const int tid  = threadIdx.x;
    const int wid  = tid >> 5;
    const int lane = tid & 31;
    const int pbase = bid * 32;

    if (task == 0) {
        // ------------------------- gather1 -------------------------
        #pragma unroll
        for (int i = 0; i < 2; i++) {
            int e = tid + i * 256;
            int pp = pbase + (e >> 4);
            is[e >> 4][e & 15] = (pp < N) ? idx[(size_t)pp * 16 + (e & 15)] : 0;
        }
        __syncthreads();

        const int pl = wid * 4 + (lane >> 3);
        const int sl = lane & 7;
        const int p  = pbase + pl;
        if (p >= N) return;

        const uint4* src = reinterpret_cast<const uint4*>(a0h);
        float s[8];
        #pragma unroll
        for (int i = 0; i < 8; i++) s[i] = 0.f;

        #pragma unroll
        for (int k = 0; k < 16; k += 2) {
            uint4 ua = src[(size_t)is[pl][k]     * 8 + sl];
            uint4 ub = src[(size_t)is[pl][k + 1] * 8 + sl];
            __half2 h0 = __hadd2(u2h2(ua.x), u2h2(ub.x));
            __half2 h1 = __hadd2(u2h2(ua.y), u2h2(ub.y));
            __half2 h2 = __hadd2(u2h2(ua.z), u2h2(ub.z));
            __half2 h3 = __hadd2(u2h2(ua.w), u2h2(ub.w));
            float2 f0 = __half22float2(h0);
            float2 f1 = __half22float2(h1);
            float2 f2 = __half22float2(h2);
            float2 f3 = __half22float2(h3);
            s[0] += f0.x; s[1] += f0.y; s[2] += f1.x; s[3] += f1.y;
            s[4] += f2.x; s[5] += f2.y; s[6] += f3.x; s[7] += f3.y;
        }

        __half2 o0 = __float22half2_rn(make_float2(s[0] * 0.0625f, s[1] * 0.0625f));
        __half2 o1 = __float22half2_rn(make_float2(s[2] * 0.0625f, s[3] * 0.0625f));
        __half2 o2 = __float22half2_rn(make_float2(s[4] * 0.0625f, s[5] * 0.0625f));
        __half2 o3 = __float22half2_rn(make_float2(s[6] * 0.0625f, s[7] * 0.0625f));
        uint4 o;
        o.x = *reinterpret_cast<uint32_t*>(&o0);
        o.y = *reinterpret_cast<uint32_t*>(&o1);
        o.z = *reinterpret_cast<uint32_t*>(&o2);
        o.w = *reinterpret_cast<uint32_t*>(&o3);
        *reinterpret_cast<uint4*>(a1h + (size_t)p * 128 + 64 + sl * 8) = o;
        return;
    }

    // ------------------------- geom MLP (32 pts) -------------------------
    #pragma unroll
    for (int i = 0; i < 2; i++) {
        int e = tid + i * 256;
        int pp = pbase + (e >> 4);
        int k  = e & 15;
        float4 gv = (pp < N)
            ? reinterpret_cast<const float4*>(geom)[(size_t)pp * 16 + k]
            : make_float4(0.f, 0.f, 0.f, 0.f);
        __half2 g01 = __float22half2_rn(make_float2(gv.x, gv.y));
        __half2 g23 = __float22half2_rn(make_float2(gv.z, gv.w));
        uint2 u;
        u.x = *reinterpret_cast<uint32_t*>(&g01);
        u.y = *reinterpret_cast<uint32_t*>(&g23);
        gsm[e >> 4][k] = u;
    }
    __syncthreads();

    const int ch0 = lane * 6;
    __half2 w0[3], w1[3], w2[3], w3[3], bb[3];
    #pragma unroll
    for (int j = 0; j < 3; j++) {
        int ch = ch0 + 2 * j;
        const float* wsrc;
        const float* bsrc;
        int str, cb;
        if (ch < 64) { wsrc = wg1; bsrc = bg1; str = 64;  cb = ch; }
        else         { wsrc = wg2; bsrc = bg2; str = 128; cb = ch - 64; }
        w0[j] = __floats2half2_rn(wsrc[0 * str + cb], wsrc[0 * str + cb + 1]);
        w1[j] = __floats2half2_rn(wsrc[1 * str + cb], wsrc[1 * str + cb + 1]);
        w2[j] = __floats2half2_rn(wsrc[2 * str + cb], wsrc[2 * str + cb + 1]);
        w3[j] = __floats2half2_rn(wsrc[3 * str + cb], wsrc[3 * str + cb + 1]);
        bb[j] = __floats2half2_rn(bsrc[cb], bsrc[cb + 1]);
    }

    const __half2 zero = __float2half2_rn(0.0f);
    const __half2 p02  = __float2half2_rn(0.2f);

    #pragma unroll
    for (int it = 0; it < 4; it++) {
        const int pl = it * 8 + wid;
        const int p  = pbase + pl;
        if (p >= N) continue;

        float acc[6];
        #pragma unroll
        for (int i = 0; i < 6; i++) acc[i] = 0.0f;

        #pragma unroll
        for (int k = 0; k < 16; k++) {
            uint2 u = gsm[pl][k];
            __half2 g01 = u2h2(u.x);
            __half2 g23 = u2h2(u.y);
            __half2 gb0 = __low2half2(g01);
            __half2 gb1 = __high2half2(g01);
            __half2 gb2 = __low2half2(g23);
            __half2 gb3 = __high2half2(g23);
            #pragma unroll
            for (int j = 0; j < 3; j++) {
                __half2 v = bb[j];
                v = __hfma2(gb0, w0[j], v);
                v = __hfma2(gb1, w1[j], v);
                v = __hfma2(gb2, w2[j], v);
                v = __hfma2(gb3, w3[j], v);
                __half2 lk = __hfma2(__hmin2(v, zero), p02, __hmax2(v, zero));
                float2 f = __half22float2(lk);
                acc[2 * j]     += f.x;
                acc[2 * j + 1] += f.y;
            }
        }

        #pragma unroll
        for (int j = 0; j < 3; j++) {
            int ch = ch0 + 2 * j;
            __half2 o = __float22half2_rn(
                make_float2(acc[2 * j] * 0.0625f, acc[2 * j + 1] * 0.0625f));
            if (ch < 64)
                *reinterpret_cast<uint32_t*>(a1h + (size_t)p * 128 + ch) =
                    *reinterpret_cast<uint32_t*>(&o);
            else
                *reinterpret_cast<uint32_t*>(a2g + (size_t)p * 128 + (ch - 64)) =
                    *reinterpret_cast<uint32_t*>(&o);
        }
    }
}

// ---------------------------------------------------------------------------
// FINAL GEMM with FUSED gather2:
//   a2[row, 0:128]   = a2g[row]           (cp.async, k-stages 0,1)
//   a2[row, 128:256] = mean_k a1h[idx[row,k], 0:128]  (in-kernel gather,
//                      written to smem A-stages 2,3)
//   out = leaky(a2 @ wfT^T + b_fin) + resh
// CTA tile 64 x 256 (grid.y = 1 — each row gathered exactly once).
// smem: A[4 x 8KB static k-stages] | B[2 x 32KB double-buffered] | idx[4KB]
// ---------------------------------------------------------------------------
__global__ __launch_bounds__(256, 2)
void hgemm_fin(const __half* __restrict__ a2g, const __half* __restrict__ a1h,
               const int* __restrict__ idx,
               const __half* __restrict__ Bt, const float* __restrict__ bias,
               const __half* __restrict__ resh, float* __restrict__ C, int M)
{
    constexpr int CTAM  = 64;
    constexpr int CTAN  = 256;
    constexpr int ASTG  = CTAM * 128;        // 8 KB per k-stage
    constexpr int AOFF  = 0;                 // 4 stages: 32 KB
    constexpr int BOFF  = 4 * ASTG;          // 32768
    constexpr int BSTG  = CTAN * 128;        // 32 KB per B stage
    constexpr int IOFF  = BOFF + 2 * BSTG;   // 98304
    constexpr int NT16  = CTAN / 32;         // 8
    constexpr int NT8   = 2 * NT16;          // 16

    extern __shared__ char smem[];
    const uint32_t sbase = (uint32_t)__cvta_generic_to_shared(smem);
    int* is = reinterpret_cast<int*>(smem + IOFF);

    const int tid  = threadIdx.x;
    const int wid  = tid >> 5;
    const int lane = tid & 31;
    const int g = lane >> 2;
    const int l = lane & 3;
    const int quad = lane >> 3;
    const int lrow = lane & 7;
    const int warp_m = (wid & 3) * 16;
    const int warp_n = (wid >> 2) * (CTAN / 2);
    const int rowbase = blockIdx.x * CTAM;

    const int pa_r = tid >> 3, pa_c = tid & 7;
    const int arow  = warp_m + (quad & 1) * 8 + lrow;
    const int ac_hi = quad >> 1;
    const int brow0 = warp_n + ((quad >> 1) & 1) * 8 + lrow;
    const int bc_lo = quad & 1;

    // ---- issue A stages 0,1 (geom part) + B stage 0 as group 1 ----
    #pragma unroll
    for (int i = 0; i < 4; i++) {            // 1024 chunks: 2 stages x 64r x 8c
        int e = tid + i * 256;
        int t = e >> 9;
        int rc = e & 511;
        int r = rc >> 3, c8 = rc & 7;
        int grow = rowbase + r;
        bool v = grow < M;
        const __half* src = a2g + (size_t)(v ? grow : 0) * 128 + t * 64 + c8 * 8;
        uint32_t dst = sbase + AOFF + t * ASTG + r * 128 + ((c8 ^ (r & 7)) << 4);
        cp_async16(dst, src, v ? 16u : 0u);
    }
    auto issueB = [&](int t) {
        const int kk = t * 64;
        const uint32_t st = sbase + BOFF + (t & 1) * BSTG;
        #pragma unroll
        for (int i = 0; i < 8; i++) {        // 256 rows x 8 chunks / 256 thr
            int r = pa_r + i * 32;
            const __half* src = Bt + (size_t)r * 256 + kk + pa_c * 8;
            uint32_t dst = st + r * 128 + ((pa_c ^ (r & 7)) << 4);
            cp_async16(dst, src, 16u);
        }
        CP_COMMIT();
    };
    issueB(0);   // group 1 = A01 + B0
    issueB(1);   // group 2 = B1

    // ---- load idx (regular LDG/STS; independent of cp.async groups) ----
    #pragma unroll
    for (int i = 0; i < 4; i++) {            // 64 rows x 16
        int e = tid + i * 256;
        int pp = rowbase + (e >> 4);
        is[e] = (pp < M) ? idx[(size_t)pp * 16 + (e & 15)] : 0;
    }
    __syncthreads();

    // ---- in-kernel gather2: rows -> A k-stages 2,3 ----
    {
        const int r   = tid >> 2;            // 0..63
        const int seg = tid & 3;             // 32 channels each
        const uint4* src = reinterpret_cast<const uint4*>(a1h); // 16 uint4/row
        const int ubase = seg * 4;

        float s[32];
        #pragma unroll
        for (int i = 0; i < 32; i++) s[i] = 0.f;

        #pragma unroll
        for (int k = 0; k < 16; k += 2) {
            const size_t ra = (size_t)is[r * 16 + k]     * 16 + ubase;
            const size_t rb = (size_t)is[r * 16 + k + 1] * 16 + ubase;
            #pragma unroll
            for (int j = 0; j < 4; j++) {
                uint4 ua = src[ra + j];
                uint4 ub = src[rb + j];
                __half2 h0 = __hadd2(u2h2(ua.x), u2h2(ub.x));
                __half2 h1 = __hadd2(u2h2(ua.y), u2h2(ub.y));
                __half2 h2 = __hadd2(u2h2(ua.z), u2h2(ub.z));
                __half2 h3 = __hadd2(u2h2(ua.w), u2h2(ub.w));
                float2 f0 = __half22float2(h0);
                float2 f1 = __half22float2(h1);
                float2 f2 = __half22float2(h2);
                float2 f3 = __half22float2(h3);
                s[j * 8 + 0] += f0.x; s[j * 8 + 1] += f0.y;
                s[j * 8 + 2] += f1.x; s[j * 8 + 3] += f1.y;
                s[j * 8 + 4] += f2.x; s[j * 8 + 5] += f2.y;
                s[j * 8 + 6] += f3.x; s[j * 8 + 7] += f3.y;
            }
        }

        // write 32 halves to A stage 2+(seg>>1), chunks (seg&1)*4 .. +3
        const int gs    = 2 + (seg >> 1);
        const int cbase = (seg & 1) * 4;
        char* gdst = smem + AOFF + gs * ASTG + r * 128;
        #pragma unroll
        for (int j = 0; j < 4; j++) {
            __half2 p0 = __float22half2_rn(
                make_float2(s[j * 8 + 0] * 0.0625f, s[j * 8 + 1] * 0.0625f));
            __half2 p1 = __float22half2_rn(
                make_float2(s[j * 8 + 2] * 0.0625f, s[j * 8 + 3] * 0.0625f));
            __half2 p2 = __float22half2_rn(
                make_float2(s[j * 8 + 4] * 0.0625f, s[j * 8 + 5] * 0.0625f));
            __half2 p3 = __float22half2_rn(
                make_float2(s[j * 8 + 6] * 0.0625f, s[j * 8 + 7] * 0.0625f));
            uint4 o;
            o.x = *reinterpret_cast<uint32_t*>(&p0);
            o.y = *reinterpret_cast<uint32_t*>(&p1);
            o.z = *reinterpret_cast<uint32_t*>(&p2);
            o.w = *reinterpret_cast<uint32_t*>(&p3);
            int c8 = cbase + j;
            *reinterpret_cast<uint4*>(gdst + ((c8 ^ (r & 7)) << 4)) = o;
        }
    }

    float c[NT8][4];
    #pragma unroll
    for (int ni = 0; ni < NT8; ni++)
        #pragma unroll
        for (int j = 0; j < 4; j++)
            c[ni][j] = 0.0f;

    CP_WAIT(1);          // group1 (A01+B0) done
    __syncthreads();     // gather writes + idx visible

    for (int t = 0; t < 4; t++) {
        const uint32_t ast = sbase + AOFF + t * ASTG;
        const uint32_t bst = sbase + BOFF + (t & 1) * BSTG;
        #pragma unroll
        for (int ks8 = 0; ks8 < 8; ks8 += 2) {
            uint32_t af[4];
            {
                int cch = ks8 + ac_hi;
                uint32_t addr = ast + arow * 128 + ((cch ^ (arow & 7)) << 4);
                LDSM_X4(af[0], af[1], af[2], af[3], addr);
            }
            #pragma unroll
            for (int nt = 0; nt < NT16; nt++) {
                uint32_t bf[4];
                int r = brow0 + nt * 16;
                int cch = ks8 + bc_lo;
                uint32_t addr = bst + r * 128 + ((cch ^ (r & 7)) << 4);
                LDSM_X4(bf[0], bf[1], bf[2], bf[3], addr);
                MMA_F16(c[nt * 2 + 0], af, bf[0], bf[1]);
                MMA_F16(c[nt * 2 + 1], af, bf[2], bf[3]);
            }
        }
        __syncthreads();
        if (t + 1 < 4) {
            if (t + 2 < 4) { issueB(t + 2); CP_WAIT(1); }
            else           { CP_WAIT(0); }
            __syncthreads();
        }
    }

    // ---- epilogue: bias + leaky + half residual, fp32 out ----
    #pragma unroll
    for (int ni = 0; ni < NT8; ni++) {
        const int col = warp_n + ni * 8 + 2 * l;
        const float b0 = bias[col];
        const float b1 = bias[col + 1];
        #pragma unroll
        for (int hm = 0; hm < 2; hm++) {
            const int r = rowbase + warp_m + g + hm * 8;
            if (r >= M) continue;
            uint32_t ru = *reinterpret_cast<const uint32_t*>(
                resh + (size_t)r * 256 + col);
            float2 rv = __half22float2(u2h2(ru));
            float2 o;
            o.x = leaky(c[ni][hm * 2 + 0] + b0) + rv.x;
            o.y = leaky(c[ni][hm * 2 + 1] + b1) + rv.y;
            *reinterpret_cast<float2*>(C + (size_t)r * 256 + col) = o;
        }
    }
}

// ---------------------------------------------------------------------------
extern "C" void kernel_launch(void* const* d_in, const int* in_sizes, int n_in,
                              void* d_out, int out_size)
{
    const float* X      = (const float*)d_in[0];
    const float* geom   = (const float*)d_in[1];
    const int*   idx    = (const int*)  d_in[2];
    const float* w_res  = (const float*)d_in[3];
    const float* b_res  = (const float*)d_in[4];
    const float* w_init = (const float*)d_in[5];
    const float* b_init = (const float*)d_in[6];
    const float* w_g1   = (const float*)d_in[7];
    const float* b_g1   = (const float*)d_in[8];
    const float* w_g2   = (const float*)d_in[9];
    const float* b_g2   = (const float*)d_in[10];
    const float* w_fin  = (const float*)d_in[11];
    const float* b_fin  = (const float*)d_in[12];
    float* out = (float*)d_out;

    const int N = in_sizes[0] / DIM;

    __half *resh, *a0h, *a1h, *a2g, *wcat, *wfT;
    cudaGetSymbolAddress((void**)&resh, g_resh);
    cudaGetSymbolAddress((void**)&a0h,  g_a0h);
    cudaGetSymbolAddress((void**)&a1h,  g_a1h);
    cudaGetSymbolAddress((void**)&a2g,  g_a2g);
    cudaGetSymbolAddress((void**)&wcat, g_wcat);
    cudaGetSymbolAddress((void**)&wfT,  g_wfT);

    constexpr int SMEM_CAT = 2 * (64 * 128 + 320 * 128);          // 96 KB
    constexpr int SMEM_FIN = 4 * 8192 + 2 * 32768 + 4096;         // 100 KB
    cudaFuncSetAttribute(hgemm_cat,
                         cudaFuncAttributeMaxDynamicSharedMemorySize, SMEM_CAT);
    cudaFuncSetAttribute(hgemm_fin,
                         cudaFuncAttributeMaxDynamicSharedMemorySize, SMEM_FIN);

    const int nG32 = (N + 31) / 32;

    // 0) weight prep
    prep_w<<<144, 256>>>(w_res, w_init, w_fin, wcat, wfT);
    // 1+2) fused: resh (half) + a0h (half) = leaky(X @ [w_res|w_init] + b)
    hgemm_cat<<<dim3((N + 63) / 64, 1), 256, SMEM_CAT>>>(
        X, wcat, b_res, b_init, resh, a0h, N);
    // 3) merged: gather1 (even blocks) + geometry MLP (odd blocks)
    geo_g1<<<2 * nG32, 256>>>(geom, w_g1, b_g1, w_g2, b_g2,
                              a0h, idx, a1h, a2g, N);
    // 4+5) fused: gather2 + final GEMM + residual
    hgemm_fin<<<dim3((N + 63) / 64, 1), 256, SMEM_FIN>>>(
        a2g, a1h, idx, wfT, b_fin, resh, out, N);
}

// round 14
// speedup vs baseline: 1.1517x; 1.1517x over previous
#include <cuda_runtime.h>
#include <cuda_fp16.h>
#include <cstdint>

#define NPTS 50000
#define DIM 256

// ---------------- scratch (no-alloc rule: __device__ globals) --------------
__device__ __half g_resh[NPTS * DIM];       // residual, half
__device__ __half g_a0h[NPTS * (DIM / 4)];  // init MLP out, half
__device__ __half g_a1h[NPTS * (DIM / 2)];  // LFA1 out, half
__device__ __half g_a2h[NPTS * DIM];        // LFA2 out, half
__device__ __half g_wcat[(DIM + DIM / 4) * DIM]; // [w_res^T ; w_init^T] [320,256]
__device__ __half g_wfT[DIM * DIM];         // w_fin^T half [256,256]

__device__ __forceinline__ float leaky(float x) {
    return x >= 0.0f ? x : 0.2f * x;
}

#define MMA_F16(c, a, b0, b1)                                             \
    asm volatile(                                                         \
        "mma.sync.aligned.m16n8k16.row.col.f32.f16.f16.f32 "              \
        "{%0,%1,%2,%3}, {%4,%5,%6,%7}, {%8,%9}, {%0,%1,%2,%3};"           \
        : "+f"((c)[0]), "+f"((c)[1]), "+f"((c)[2]), "+f"((c)[3])          \
        : "r"((a)[0]), "r"((a)[1]), "r"((a)[2]), "r"((a)[3]),             \
          "r"(b0), "r"(b1))

#define LDSM_X4(r0, r1, r2, r3, addr)                                     \
    asm volatile(                                                         \
        "ldmatrix.sync.aligned.m8n8.x4.shared.b16 {%0,%1,%2,%3}, [%4];"   \
        : "=r"(r0), "=r"(r1), "=r"(r2), "=r"(r3) : "r"(addr))

__device__ __forceinline__ void cp_async16(uint32_t dst, const void* src,
                                           uint32_t src_bytes) {
    asm volatile("cp.async.ca.shared.global [%0], [%1], 16, %2;"
                 :: "r"(dst), "l"(src), "r"(src_bytes));
}
#define CP_COMMIT() asm volatile("cp.async.commit_group;")
#define CP_WAIT(n)  asm volatile("cp.async.wait_group %0;" :: "n"(n))

__device__ __forceinline__ __half2 u2h2(uint32_t u) {
    return *reinterpret_cast<__half2*>(&u);
}

// ---------------------------------------------------------------------------
// prep_w: fp32 [K,N] -> half [N,K] for the three GEMM weights (144 blocks).
// ---------------------------------------------------------------------------
__global__ __launch_bounds__(256)
void prep_w(const float* __restrict__ w_res,
            const float* __restrict__ w_init,
            const float* __restrict__ w_fin,
            __half* __restrict__ wcat, __half* __restrict__ wfT)
{
    __shared__ float t[32][33];
    const int tid = threadIdx.x;
    const float* in;
    __half* out;
    int K = 256, Nc, bx;
    if (blockIdx.x < 64)      { in = w_res;  out = wcat; Nc = 256; bx = blockIdx.x; }
    else if (blockIdx.x < 80) { in = w_init; out = wcat + 256 * 256; Nc = 64;
                                bx = blockIdx.x - 64; }
    else                      { in = w_fin;  out = wfT;  Nc = 256; bx = blockIdx.x - 80; }
    int tx = tid & 31, ty = tid >> 5;
    int nTx = Nc / 32;
    int n0 = (bx % nTx) * 32;
    int k0 = (bx / nTx) * 32;
    for (int i = ty; i < 32; i += 8)
        t[i][tx] = in[(size_t)(k0 + i) * Nc + n0 + tx];
    __syncthreads();
    for (int i = ty; i < 32; i += 8)
        out[(size_t)(n0 + i) * K + k0 + tx] = __float2half(t[tx][i]);
}

// ---------------------------------------------------------------------------
// CAT GEMM (fused stage 1+2): CTA tile 64 x 320, grid.y = 1 — single X pass.
// ---------------------------------------------------------------------------
__global__ __launch_bounds__(256, 2)
void hgemm_cat(const float* __restrict__ A, const __half* __restrict__ Bt,
               const float* __restrict__ bias0, const float* __restrict__ bias1,
               __half* __restrict__ resh, __half* __restrict__ a0h, int M)
{
    constexpr int KD    = 256;
    constexpr int BK    = 64;
    constexpr int NST   = KD / BK;           // 4
    constexpr int CTAM  = 64;
    constexpr int CTAN  = 320;
    constexpr int ABY   = CTAM * 128;        // 8 KB
    constexpr int BBY   = CTAN * 128;        // 40 KB
    constexpr int STAGE = ABY + BBY;         // 48 KB
    constexpr int NT16  = CTAN / 32;         // 10
    constexpr int NT8   = 2 * NT16;          // 20

    extern __shared__ char smem[];
    const uint32_t sbase = (uint32_t)__cvta_generic_to_shared(smem);

    const int tid  = threadIdx.x;
    const int wid  = tid >> 5;
    const int lane = tid & 31;
    const int g = lane >> 2;
    const int l = lane & 3;
    const int quad = lane >> 3;
    const int lrow = lane & 7;
    const int warp_m = (wid & 3) * 16;
    const int warp_n = (wid >> 2) * (CTAN / 2);
    const int rowbase = blockIdx.x * CTAM;

    const int pa_r = tid >> 3, pa_c = tid & 7;

    const int arow  = warp_m + (quad & 1) * 8 + lrow;
    const int ac_hi = quad >> 1;
    const int brow0 = warp_n + ((quad >> 1) & 1) * 8 + lrow;
    const int bc_lo = quad & 1;

    float c[NT8][4];
    #pragma unroll
    for (int ni = 0; ni < NT8; ni++)
        #pragma unroll
        for (int j = 0; j < 4; j++)
            c[ni][j] = 0.0f;

    float4 aR[2][2];

    auto ldgA = [&](int t) {
        const int kk = t * BK;
        #pragma unroll
        for (int i = 0; i < 2; i++) {
            int hc = tid + i * 256;
            int r = hc >> 3, c8 = hc & 7;
            int grow = rowbase + r;
            if (grow < M) {
                const float4* src = reinterpret_cast<const float4*>(
                    A + (size_t)grow * KD + kk + c8 * 8);
                aR[i][0] = src[0];
                aR[i][1] = src[1];
            } else {
                aR[i][0] = make_float4(0.f, 0.f, 0.f, 0.f);
                aR[i][1] = make_float4(0.f, 0.f, 0.f, 0.f);
            }
        }
    };

    auto storeA = [&](int t) {
        char* st = smem + (t & 1) * STAGE;
        #pragma unroll
        for (int i = 0; i < 2; i++) {
            int hc = tid + i * 256;
            int r = hc >> 3, c8 = hc & 7;
            __half2 h0 = __float22half2_rn(make_float2(aR[i][0].x, aR[i][0].y));
            __half2 h1 = __float22half2_rn(make_float2(aR[i][0].z, aR[i][0].w));
            __half2 h2 = __float22half2_rn(make_float2(aR[i][1].x, aR[i][1].y));
            __half2 h3 = __float22half2_rn(make_float2(aR[i][1].z, aR[i][1].w));
            uint4 v;
            v.x = *reinterpret_cast<uint32_t*>(&h0);
            v.y = *reinterpret_cast<uint32_t*>(&h1);
            v.z = *reinterpret_cast<uint32_t*>(&h2);
            v.w = *reinterpret_cast<uint32_t*>(&h3);
            *reinterpret_cast<uint4*>(
                st + r * 128 + ((c8 ^ (r & 7)) << 4)) = v;
        }
    };

    auto issueB = [&](int t) {
        const int kk = t * BK;
        const uint32_t st = sbase + (t & 1) * STAGE;
        #pragma unroll
        for (int i = 0; i < 10; i++) {
            int r = pa_r + i * 32;
            const __half* src =
                Bt + (size_t)r * KD + kk + pa_c * 8;
            uint32_t dst = st + ABY + r * 128 + ((pa_c ^ (r & 7)) << 4);
            cp_async16(dst, src, 16u);
        }
        CP_COMMIT();
    };

    ldgA(0);
    issueB(0);
    issueB(1);
    storeA(0);
    CP_WAIT(1);
    __syncthreads();

    for (int t = 0; t < NST; t++) {
        const uint32_t st = sbase + (t & 1) * STAGE;
        if (t + 1 < NST) ldgA(t + 1);

        #pragma unroll
        for (int ks8 = 0; ks8 < BK / 8; ks8 += 2) {
            uint32_t af[4];
            {
                int cch = ks8 + ac_hi;
                uint32_t addr = st + arow * 128 + ((cch ^ (arow & 7)) << 4);
                LDSM_X4(af[0], af[1], af[2], af[3], addr);
            }
            #pragma unroll
            for (int nt = 0; nt < NT16; nt++) {
                uint32_t bf[4];
                int r = brow0 + nt * 16;
                int cch = ks8 + bc_lo;
                uint32_t addr = st + ABY + r * 128 + ((cch ^ (r & 7)) << 4);
                LDSM_X4(bf[0], bf[1], bf[2], bf[3], addr);
                MMA_F16(c[nt * 2 + 0], af, bf[0], bf[1]);
                MMA_F16(c[nt * 2 + 1], af, bf[2], bf[3]);
            }
        }
        __syncthreads();
        if (t + 1 < NST) {
            storeA(t + 1);
            if (t + 2 < NST) { issueB(t + 2); CP_WAIT(1); }
            else             { CP_WAIT(0); }
            __syncthreads();
        }
    }

    #pragma unroll
    for (int ni = 0; ni < NT8; ni++) {
        const int col = warp_n + ni * 8 + 2 * l;
        const bool isInit = (col >= 256);
        const float b0 = isInit ? bias1[col - 256] : bias0[col];
        const float b1 = isInit ? bias1[col - 255] : bias0[col + 1];
        #pragma unroll
        for (int hm = 0; hm < 2; hm++) {
            const int r = rowbase + warp_m + g + hm * 8;
            if (r >= M) continue;
            float ox = leaky(c[ni][hm * 2 + 0] + b0);
            float oy = leaky(c[ni][hm * 2 + 1] + b1);
            __half2 h = __float22half2_rn(make_float2(ox, oy));
            if (isInit)
                *reinterpret_cast<uint32_t*>(
                    a0h + (size_t)r * 64 + col - 256) =
                    *reinterpret_cast<uint32_t*>(&h);
            else
                *reinterpret_cast<uint32_t*>(
                    resh + (size_t)r * 256 + col) =
                    *reinterpret_cast<uint32_t*>(&h);
        }
    }
}

// ---------------------------------------------------------------------------
// geo_g1: merged launch, interleaved tasks per blockIdx parity.
//   task 0 (even): gather1  — a1h[p,64:128] = mean_k a0h[idx[p,k], :]
//   task 1 (odd):  geom MLP — a1h[p,0:64], a2h[p,0:128]
// ---------------------------------------------------------------------------
__global__ __launch_bounds__(256)
void geo_g1(const float* __restrict__ geom,
            const float* __restrict__ wg1, const float* __restrict__ bg1,
            const float* __restrict__ wg2, const float* __restrict__ bg2,
            const __half* __restrict__ a0h, const int* __restrict__ idx,
            __half* __restrict__ a1h, __half* __restrict__ a2h, int N)
{
    __shared__ int   is[32][16];
    __shared__ uint2 gsm[32][16];

    const int task = blockIdx.x & 1;
    const int bid  = blockIdx.x >> 1;
    const int tid  = threadIdx.x;
    const int wid  = tid >> 5;
    const int lane = tid & 31;
    const int pbase = bid * 32;

    if (task == 0) {
        // ------------------------- gather1 -------------------------
        #pragma unroll
        for (int i = 0; i < 2; i++) {
            int e = tid + i * 256;
            int pp = pbase + (e >> 4);
            is[e >> 4][e & 15] = (pp < N) ? idx[(size_t)pp * 16 + (e & 15)] : 0;
        }
        __syncthreads();

        const int pl = wid * 4 + (lane >> 3);
        const int sl = lane & 7;
        const int p  = pbase + pl;
        if (p >= N) return;

        const uint4* src = reinterpret_cast<const uint4*>(a0h);
        float s[8];
        #pragma unroll
        for (int i = 0; i < 8; i++) s[i] = 0.f;

        #pragma unroll
        for (int k = 0; k < 16; k += 2) {
            uint4 ua = src[(size_t)is[pl][k]     * 8 + sl];
            uint4 ub = src[(size_t)is[pl][k + 1] * 8 + sl];
            __half2 h0 = __hadd2(u2h2(ua.x), u2h2(ub.x));
            __half2 h1 = __hadd2(u2h2(ua.y), u2h2(ub.y));
            __half2 h2 = __hadd2(u2h2(ua.z), u2h2(ub.z));
            __half2 h3 = __hadd2(u2h2(ua.w), u2h2(ub.w));
            float2 f0 = __half22float2(h0);
            float2 f1 = __half22float2(h1);
            float2 f2 = __half22float2(h2);
            float2 f3 = __half22float2(h3);
            s[0] += f0.x; s[1] += f0.y; s[2] += f1.x; s[3] += f1.y;
            s[4] += f2.x; s[5] += f2.y; s[6] += f3.x; s[7] += f3.y;
        }

        __half2 o0 = __float22half2_rn(make_float2(s[0] * 0.0625f, s[1] * 0.0625f));
        __half2 o1 = __float22half2_rn(make_float2(s[2] * 0.0625f, s[3] * 0.0625f));
        __half2 o2 = __float22half2_rn(make_float2(s[4] * 0.0625f, s[5] * 0.0625f));
        __half2 o3 = __float22half2_rn(make_float2(s[6] * 0.0625f, s[7] * 0.0625f));
        uint4 o;
        o.x = *reinterpret_cast<uint32_t*>(&o0);
        o.y = *reinterpret_cast<uint32_t*>(&o1);
        o.z = *reinterpret_cast<uint32_t*>(&o2);
        o.w = *reinterpret_cast<uint32_t*>(&o3);
        *reinterpret_cast<uint4*>(a1h + (size_t)p * 128 + 64 + sl * 8) = o;
        return;
    }

    // ------------------------- geom MLP (32 pts) -------------------------
    #pragma unroll
    for (int i = 0; i < 2; i++) {
        int e = tid + i * 256;
        int pp = pbase + (e >> 4);
        int k  = e & 15;
        float4 gv = (pp < N)
            ? reinterpret_cast<const float4*>(geom)[(size_t)pp * 16 + k]
            : make_float4(0.f, 0.f, 0.f, 0.f);
        __half2 g01 = __float22half2_rn(make_float2(gv.x, gv.y));
        __half2 g23 = __float22half2_rn(make_float2(gv.z, gv.w));
        uint2 u;
        u.x = *reinterpret_cast<uint32_t*>(&g01);
        u.y = *reinterpret_cast<uint32_t*>(&g23);
        gsm[e >> 4][k] = u;
    }
    __syncthreads();

    const int ch0 = lane * 6;
    __half2 w0[3], w1[3], w2[3], w3[3], bb[3];
    #pragma unroll
    for (int j = 0; j < 3; j++) {
        int ch = ch0 + 2 * j;
        const float* wsrc;
        const float* bsrc;
        int str, cb;
        if (ch < 64) { wsrc = wg1; bsrc = bg1; str = 64;  cb = ch; }
        else         { wsrc = wg2; bsrc = bg2; str = 128; cb = ch - 64; }
        w0[j] = __floats2half2_rn(wsrc[0 * str + cb], wsrc[0 * str + cb + 1]);
        w1[j] = __floats2half2_rn(wsrc[1 * str + cb], wsrc[1 * str + cb + 1]);
        w2[j] = __floats2half2_rn(wsrc[2 * str + cb], wsrc[2 * str + cb + 1]);
        w3[j] = __floats2half2_rn(wsrc[3 * str + cb], wsrc[3 * str + cb + 1]);
        bb[j] = __floats2half2_rn(bsrc[cb], bsrc[cb + 1]);
    }

    const __half2 zero = __float2half2_rn(0.0f);
    const __half2 p02  = __float2half2_rn(0.2f);

    #pragma unroll
    for (int it = 0; it < 4; it++) {
        const int pl = it * 8 + wid;
        const int p  = pbase + pl;
        if (p >= N) continue;

        float acc[6];
        #pragma unroll
        for (int i = 0; i < 6; i++) acc[i] = 0.0f;

        #pragma unroll
        for (int k = 0; k < 16; k++) {
            uint2 u = gsm[pl][k];
            __half2 g01 = u2h2(u.x);
            __half2 g23 = u2h2(u.y);
            __half2 gb0 = __low2half2(g01);
            __half2 gb1 = __high2half2(g01);
            __half2 gb2 = __low2half2(g23);
            __half2 gb3 = __high2half2(g23);
            #pragma unroll
            for (int j = 0; j < 3; j++) {
                __half2 v = bb[j];
                v = __hfma2(gb0, w0[j], v);
                v = __hfma2(gb1, w1[j], v);
                v = __hfma2(gb2, w2[j], v);
                v = __hfma2(gb3, w3[j], v);
                __half2 lk = __hfma2(__hmin2(v, zero), p02, __hmax2(v, zero));
                float2 f = __half22float2(lk);
                acc[2 * j]     += f.x;
                acc[2 * j + 1] += f.y;
            }
        }

        #pragma unroll
        for (int j = 0; j < 3; j++) {
            int ch = ch0 + 2 * j;
            __half2 o = __float22half2_rn(
                make_float2(acc[2 * j] * 0.0625f, acc[2 * j + 1] * 0.0625f));
            if (ch < 64)
                *reinterpret_cast<uint32_t*>(a1h + (size_t)p * 128 + ch) =
                    *reinterpret_cast<uint32_t*>(&o);
            else
                *reinterpret_cast<uint32_t*>(a2h + (size_t)p * 256 + (ch - 64)) =
                    *reinterpret_cast<uint32_t*>(&o);
        }
    }
}

// ---------------------------------------------------------------------------
// gather2: a2h[p, 128:256] = mean_k a1h[idx[p,k], 0:128]
// ---------------------------------------------------------------------------
__global__ __launch_bounds__(256)
void gather2(const __half* __restrict__ a1h, const int* __restrict__ idx,
             __half* __restrict__ a2h, int N)
{
    __shared__ int is[16][16];
    const int tid  = threadIdx.x;
    const int wid  = tid >> 5;
    const int lane = tid & 31;
    const int pbase = blockIdx.x * 16;

    {
        int pp = pbase + (tid >> 4);
        is[tid >> 4][tid & 15] =
            (pp < N) ? idx[(size_t)pp * 16 + (tid & 15)] : 0;
    }
    __syncthreads();

    const int pl = wid * 2 + (lane >> 4);
    const int sl = lane & 15;
    const int p  = pbase + pl;
    if (p >= N) return;

    const uint4* src = reinterpret_cast<const uint4*>(a1h);
    float s[8];
    #pragma unroll
    for (int i = 0; i < 8; i++) s[i] = 0.f;

    #pragma unroll
    for (int k = 0; k < 16; k += 2) {
        uint4 ua = src[(size_t)is[pl][k]     * 16 + sl];
        uint4 ub = src[(size_t)is[pl][k + 1] * 16 + sl];
        __half2 h0 = __hadd2(u2h2(ua.x), u2h2(ub.x));
        __half2 h1 = __hadd2(u2h2(ua.y), u2h2(ub.y));
        __half2 h2 = __hadd2(u2h2(ua.z), u2h2(ub.z));
        __half2 h3 = __hadd2(u2h2(ua.w), u2h2(ub.w));
        float2 f0 = __half22float2(h0);
        float2 f1 = __half22float2(h1);
        float2 f2 = __half22float2(h2);
        float2 f3 = __half22float2(h3);
        s[0] += f0.x; s[1] += f0.y; s[2] += f1.x; s[3] += f1.y;
        s[4] += f2.x; s[5] += f2.y; s[6] += f3.x; s[7] += f3.y;
    }

    __half2 o0 = __float22half2_rn(make_float2(s[0] * 0.0625f, s[1] * 0.0625f));
    __half2 o1 = __float22half2_rn(make_float2(s[2] * 0.0625f, s[3] * 0.0625f));
    __half2 o2 = __float22half2_rn(make_float2(s[4] * 0.0625f, s[5] * 0.0625f));
    __half2 o3 = __float22half2_rn(make_float2(s[6] * 0.0625f, s[7] * 0.0625f));
    uint4 o;
    o.x = *reinterpret_cast<uint32_t*>(&o0);
    o.y = *reinterpret_cast<uint32_t*>(&o1);
    o.z = *reinterpret_cast<uint32_t*>(&o2);
    o.w = *reinterpret_cast<uint32_t*>(&o3);
    *reinterpret_cast<uint4*>(a2h + (size_t)p * 256 + 128 + sl * 8) = o;
}

// ---------------------------------------------------------------------------
// FINAL GEMM: out = leaky(a2h @ wfT^T + b_fin) + resh.
// CTA tile 64 x 256, grid.y = 1 — single pass over a2h.
// ---------------------------------------------------------------------------
__global__ __launch_bounds__(256, 2)
void hgemm_fin(const __half* __restrict__ A, const __half* __restrict__ Bt,
               const float* __restrict__ bias, const __half* __restrict__ resh,
               float* __restrict__ C, int M)
{
    constexpr int KD    = 256;
    constexpr int BK    = 64;
    constexpr int NST   = KD / BK;           // 4
    constexpr int CTAM  = 64;
    constexpr int CTAN  = 256;
    constexpr int ABY   = CTAM * 128;        // 8 KB
    constexpr int BBY   = CTAN * 128;        // 32 KB
    constexpr int STAGE = ABY + BBY;         // 40 KB
    constexpr int NT16  = CTAN / 32;         // 8
    constexpr int NT8   = 2 * NT16;          // 16

    extern __shared__ char smem[];
    const uint32_t sbase = (uint32_t)__cvta_generic_to_shared(smem);

    const int tid  = threadIdx.x;
    const int wid  = tid >> 5;
    const int lane = tid & 31;
    const int g = lane >> 2;
    const int l = lane & 3;
    const int quad = lane >> 3;
    const int lrow = lane & 7;
    const int warp_m = (wid & 3) * 16;
    const int warp_n = (wid >> 2) * (CTAN / 2);
    const int rowbase = blockIdx.x * CTAM;

    const int pa_r = tid >> 3, pa_c = tid & 7;
    const int arow  = warp_m + (quad & 1) * 8 + lrow;
    const int ac_hi = quad >> 1;
    const int brow0 = warp_n + ((quad >> 1) & 1) * 8 + lrow;
    const int bc_lo = quad & 1;

    float c[NT8][4];
    #pragma unroll
    for (int ni = 0; ni < NT8; ni++)
        #pragma unroll
        for (int j = 0; j < 4; j++)
            c[ni][j] = 0.0f;

    auto issue = [&](int t) {
        const int kk = t * BK;
        const uint32_t st = sbase + (t & 1) * STAGE;
        #pragma unroll
        for (int i = 0; i < 2; i++) {        // A: 64r x 8c = 512 chunks
            int e = tid + i * 256;
            int r = e >> 3, c8 = e & 7;
            int grow = rowbase + r;
            bool v = grow < M;
            const __half* src =
                A + (size_t)(v ? grow : 0) * KD + kk + c8 * 8;
            uint32_t dst = st + r * 128 + ((c8 ^ (r & 7)) << 4);
            cp_async16(dst, src, v ? 16u : 0u);
        }
        #pragma unroll
        for (int i = 0; i < 8; i++) {        // B: 256r x 8c = 2048 chunks
            int r = pa_r + i * 32;
            const __half* src =
                Bt + (size_t)r * KD + kk + pa_c * 8;
            uint32_t dst = st + ABY + r * 128 + ((pa_c ^ (r & 7)) << 4);
            cp_async16(dst, src, 16u);
        }
        CP_COMMIT();
    };

    issue(0);
    issue(1);
    CP_WAIT(1);
    __syncthreads();

    for (int t = 0; t < NST; t++) {
        const uint32_t st = sbase + (t & 1) * STAGE;
        #pragma unroll
        for (int ks8 = 0; ks8 < BK / 8; ks8 += 2) {
            uint32_t af[4];
            {
                int cch = ks8 + ac_hi;
                uint32_t addr = st + arow * 128 + ((cch ^ (arow & 7)) << 4);
                LDSM_X4(af[0], af[1], af[2], af[3], addr);
            }
            #pragma unroll
            for (int nt = 0; nt < NT16; nt++) {
                uint32_t bf[4];
                int r = brow0 + nt * 16;
                int cch = ks8 + bc_lo;
                uint32_t addr = st + ABY + r * 128 + ((cch ^ (r & 7)) << 4);
                LDSM_X4(bf[0], bf[1], bf[2], bf[3], addr);
                MMA_F16(c[nt * 2 + 0], af, bf[0], bf[1]);
                MMA_F16(c[nt * 2 + 1], af, bf[2], bf[3]);
            }
        }
        __syncthreads();
        if (t + 1 < NST) {
            if (t + 2 < NST) { issue(t + 2); CP_WAIT(1); }
            else             { CP_WAIT(0); }
            __syncthreads();
        }
    }

    // ---- epilogue: bias + leaky + half residual, fp32 out ----
    #pragma unroll
    for (int ni = 0; ni < NT8; ni++) {
        const int col = warp_n + ni * 8 + 2 * l;
        const float b0 = bias[col];
        const float b1 = bias[col + 1];
        #pragma unroll
        for (int hm = 0; hm < 2; hm++) {
            const int r = rowbase + warp_m + g + hm * 8;
            if (r >= M) continue;
            uint32_t ru = *reinterpret_cast<const uint32_t*>(
                resh + (size_t)r * 256 + col);
            float2 rv = __half22float2(u2h2(ru));
            float2 o;
            o.x = leaky(c[ni][hm * 2 + 0] + b0) + rv.x;
            o.y = leaky(c[ni][hm * 2 + 1] + b1) + rv.y;
            *reinterpret_cast<float2*>(C + (size_t)r * 256 + col) = o;
        }
    }
}

// ---------------------------------------------------------------------------
extern "C" void kernel_launch(void* const* d_in, const int* in_sizes, int n_in,
                              void* d_out, int out_size)
{
    const float* X      = (const float*)d_in[0];
    const float* geom   = (const float*)d_in[1];
    const int*   idx    = (const int*)  d_in[2];
    const float* w_res  = (const float*)d_in[3];
    const float* b_res  = (const float*)d_in[4];
    const float* w_init = (const float*)d_in[5];
    const float* b_init = (const float*)d_in[6];
    const float* w_g1   = (const float*)d_in[7];
    const float* b_g1   = (const float*)d_in[8];
    const float* w_g2   = (const float*)d_in[9];
    const float* b_g2   = (const float*)d_in[10];
    const float* w_fin  = (const float*)d_in[11];
    const float* b_fin  = (const float*)d_in[12];
    float* out = (float*)d_out;

    const int N = in_sizes[0] / DIM;

    __half *resh, *a0h, *a1h, *a2h, *wcat, *wfT;
    cudaGetSymbolAddress((void**)&resh, g_resh);
    cudaGetSymbolAddress((void**)&a0h,  g_a0h);
    cudaGetSymbolAddress((void**)&a1h,  g_a1h);
    cudaGetSymbolAddress((void**)&a2h,  g_a2h);
    cudaGetSymbolAddress((void**)&wcat, g_wcat);
    cudaGetSymbolAddress((void**)&wfT,  g_wfT);

    constexpr int SMEM_CAT = 2 * (64 * 128 + 320 * 128);   // 96 KB
    constexpr int SMEM_FIN = 2 * (64 * 128 + 256 * 128);   // 80 KB
    cudaFuncSetAttribute(hgemm_cat,
                         cudaFuncAttributeMaxDynamicSharedMemorySize, SMEM_CAT);
    cudaFuncSetAttribute(hgemm_fin,
                         cudaFuncAttributeMaxDynamicSharedMemorySize, SMEM_FIN);

    const int nG32 = (N + 31) / 32;

    // 0) weight prep
    prep_w<<<144, 256>>>(w_res, w_init, w_fin, wcat, wfT);
    // 1+2) fused: resh (half) + a0h (half) = leaky(X @ [w_res|w_init] + b)
    hgemm_cat<<<dim3((N + 63) / 64, 1), 256, SMEM_CAT>>>(
        X, wcat, b_res, b_init, resh, a0h, N);
    // 3) merged: gather1 (even blocks) + geometry MLP (odd blocks)
    geo_g1<<<2 * nG32, 256>>>(geom, w_g1, b_g1, w_g2, b_g2,
                              a0h, idx, a1h, a2h, N);
    // 4) gather half of LFA2
    gather2<<<(N + 15) / 16, 256>>>(a1h, idx, a2h, N);
    // 5) out = leaky(a2 @ w_fin + b_fin) + resh
    hgemm_fin<<<dim3((N + 63) / 64, 1), 256, SMEM_FIN>>>(
        a2h, wfT, b_fin, resh, out, N);
}

// round 15
// speedup vs baseline: 1.2001x; 1.0420x over previous
#include <cuda_runtime.h>
#include <cuda_fp16.h>
#include <cstdint>

#define NPTS 50000
#define DIM 256

// ---------------- scratch (no-alloc rule: __device__ globals) --------------
__device__ __half g_resh[NPTS * DIM];       // residual, half
__device__ __half g_a0h[NPTS * (DIM / 4)];  // init MLP out, half
__device__ __half g_a1h[NPTS * (DIM / 2)];  // LFA1 out, half
__device__ __half g_a2h[NPTS * DIM];        // LFA2 out, half
__device__ __half g_wcat[(DIM + DIM / 4) * DIM]; // [w_res^T ; w_init^T] [320,256]
__device__ __half g_wfT[DIM * DIM];         // w_fin^T half [256,256]

__device__ __forceinline__ float leaky(float x) {
    return x >= 0.0f ? x : 0.2f * x;
}

#define MMA_F16(c, a, b0, b1)                                             \
    asm volatile(                                                         \
        "mma.sync.aligned.m16n8k16.row.col.f32.f16.f16.f32 "              \
        "{%0,%1,%2,%3}, {%4,%5,%6,%7}, {%8,%9}, {%0,%1,%2,%3};"           \
        : "+f"((c)[0]), "+f"((c)[1]), "+f"((c)[2]), "+f"((c)[3])          \
        : "r"((a)[0]), "r"((a)[1]), "r"((a)[2]), "r"((a)[3]),             \
          "r"(b0), "r"(b1))

#define LDSM_X4(r0, r1, r2, r3, addr)                                     \
    asm volatile(                                                         \
        "ldmatrix.sync.aligned.m8n8.x4.shared.b16 {%0,%1,%2,%3}, [%4];"   \
        : "=r"(r0), "=r"(r1), "=r"(r2), "=r"(r3) : "r"(addr))

__device__ __forceinline__ void cp_async16(uint32_t dst, const void* src,
                                           uint32_t src_bytes) {
    asm volatile("cp.async.ca.shared.global [%0], [%1], 16, %2;"
                 :: "r"(dst), "l"(src), "r"(src_bytes));
}
#define CP_COMMIT() asm volatile("cp.async.commit_group;")
#define CP_WAIT(n)  asm volatile("cp.async.wait_group %0;" :: "n"(n))

__device__ __forceinline__ __half2 u2h2(uint32_t u) {
    return *reinterpret_cast<__half2*>(&u);
}

// ---------------------------------------------------------------------------
// prep_geom: blocks [0,144) weight prep; blocks [144,...) geometry MLP.
// ---------------------------------------------------------------------------
__global__ __launch_bounds__(256)
void prep_geom(const float* __restrict__ w_res,
               const float* __restrict__ w_init,
               const float* __restrict__ w_fin,
               __half* __restrict__ wcat, __half* __restrict__ wfT,
               const float* __restrict__ geom,
               const float* __restrict__ wg1, const float* __restrict__ bg1,
               const float* __restrict__ wg2, const float* __restrict__ bg2,
               __half* __restrict__ a1h, __half* __restrict__ a2h, int N)
{
    const int tid = threadIdx.x;

    if (blockIdx.x < 144) {
        __shared__ float t[32][33];
        const float* in;
        __half* out;
        int K = 256, Nc, bx;
        if (blockIdx.x < 64)      { in = w_res;  out = wcat; Nc = 256; bx = blockIdx.x; }
        else if (blockIdx.x < 80) { in = w_init; out = wcat + 256 * 256; Nc = 64;
                                    bx = blockIdx.x - 64; }
        else                      { in = w_fin;  out = wfT;  Nc = 256; bx = blockIdx.x - 80; }
        int tx = tid & 31, ty = tid >> 5;
        int nTx = Nc / 32;
        int n0 = (bx % nTx) * 32;
        int k0 = (bx / nTx) * 32;
        for (int i = ty; i < 32; i += 8)
            t[i][tx] = in[(size_t)(k0 + i) * Nc + n0 + tx];
        __syncthreads();
        for (int i = ty; i < 32; i += 8)
            out[(size_t)(n0 + i) * K + k0 + tx] = __float2half(t[tx][i]);
        return;
    }

    __shared__ uint2 gsm[8][16];
    const int wid  = tid >> 5;
    const int lane = tid & 31;
    const int pbase = (blockIdx.x - 144) * 8;

    if (tid < 128) {
        int pp = pbase + (tid >> 4);
        int k  = tid & 15;
        float4 gv = (pp < N)
            ? reinterpret_cast<const float4*>(geom)[(size_t)pp * 16 + k]
            : make_float4(0.f, 0.f, 0.f, 0.f);
        __half2 g01 = __float22half2_rn(make_float2(gv.x, gv.y));
        __half2 g23 = __float22half2_rn(make_float2(gv.z, gv.w));
        uint2 u;
        u.x = *reinterpret_cast<uint32_t*>(&g01);
        u.y = *reinterpret_cast<uint32_t*>(&g23);
        gsm[tid >> 4][k] = u;
    }
    __syncthreads();

    const int p = pbase + wid;
    if (p >= N) return;

    const int ch0 = lane * 6;
    __half2 w0[3], w1[3], w2[3], w3[3], bb[3];
    #pragma unroll
    for (int j = 0; j < 3; j++) {
        int ch = ch0 + 2 * j;
        const float* wsrc;
        const float* bsrc;
        int str, cb;
        if (ch < 64) { wsrc = wg1; bsrc = bg1; str = 64;  cb = ch; }
        else         { wsrc = wg2; bsrc = bg2; str = 128; cb = ch - 64; }
        w0[j] = __floats2half2_rn(wsrc[0 * str + cb], wsrc[0 * str + cb + 1]);
        w1[j] = __floats2half2_rn(wsrc[1 * str + cb], wsrc[1 * str + cb + 1]);
        w2[j] = __floats2half2_rn(wsrc[2 * str + cb], wsrc[2 * str + cb + 1]);
        w3[j] = __floats2half2_rn(wsrc[3 * str + cb], wsrc[3 * str + cb + 1]);
        bb[j] = __floats2half2_rn(bsrc[cb], bsrc[cb + 1]);
    }

    const __half2 zero = __float2half2_rn(0.0f);
    const __half2 p02  = __float2half2_rn(0.2f);
    float acc[6];
    #pragma unroll
    for (int i = 0; i < 6; i++) acc[i] = 0.0f;

    #pragma unroll
    for (int k = 0; k < 16; k++) {
        uint2 u = gsm[wid][k];
        __half2 g01 = u2h2(u.x);
        __half2 g23 = u2h2(u.y);
        __half2 gb0 = __low2half2(g01);
        __half2 gb1 = __high2half2(g01);
        __half2 gb2 = __low2half2(g23);
        __half2 gb3 = __high2half2(g23);
        #pragma unroll
        for (int j = 0; j < 3; j++) {
            __half2 v = bb[j];
            v = __hfma2(gb0, w0[j], v);
            v = __hfma2(gb1, w1[j], v);
            v = __hfma2(gb2, w2[j], v);
            v = __hfma2(gb3, w3[j], v);
            __half2 lk = __hfma2(__hmin2(v, zero), p02, __hmax2(v, zero));
            float2 f = __half22float2(lk);
            acc[2 * j]     += f.x;
            acc[2 * j + 1] += f.y;
        }
    }

    #pragma unroll
    for (int j = 0; j < 3; j++) {
        int ch = ch0 + 2 * j;
        __half2 o = __float22half2_rn(
            make_float2(acc[2 * j] * 0.0625f, acc[2 * j + 1] * 0.0625f));
        if (ch < 64)
            *reinterpret_cast<uint32_t*>(a1h + (size_t)p * 128 + ch) =
                *reinterpret_cast<uint32_t*>(&o);
        else
            *reinterpret_cast<uint32_t*>(a2h + (size_t)p * 256 + (ch - 64)) =
                *reinterpret_cast<uint32_t*>(&o);
    }
}

// ---------------------------------------------------------------------------
// CAT GEMM (fused stage 1+2): CTA tile 64 x 320, grid.y = 1 — single X pass.
// A = X fp32 [M,256] (inline cvt at STS); B = wcat half [320,256] k-major.
// ---------------------------------------------------------------------------
__global__ __launch_bounds__(256, 2)
void hgemm_cat(const float* __restrict__ A, const __half* __restrict__ Bt,
               const float* __restrict__ bias0, const float* __restrict__ bias1,
               __half* __restrict__ resh, __half* __restrict__ a0h, int M)
{
    constexpr int KD    = 256;
    constexpr int BK    = 64;
    constexpr int NST   = KD / BK;           // 4
    constexpr int CTAM  = 64;
    constexpr int CTAN  = 320;
    constexpr int ABY   = CTAM * 128;        // 8 KB
    constexpr int BBY   = CTAN * 128;        // 40 KB
    constexpr int STAGE = ABY + BBY;         // 48 KB
    constexpr int NT16  = CTAN / 32;         // 10
    constexpr int NT8   = 2 * NT16;          // 20

    extern __shared__ char smem[];
    const uint32_t sbase = (uint32_t)__cvta_generic_to_shared(smem);

    const int tid  = threadIdx.x;
    const int wid  = tid >> 5;
    const int lane = tid & 31;
    const int g = lane >> 2;
    const int l = lane & 3;
    const int quad = lane >> 3;
    const int lrow = lane & 7;
    const int warp_m = (wid & 3) * 16;
    const int warp_n = (wid >> 2) * (CTAN / 2);
    const int rowbase = blockIdx.x * CTAM;

    const int pa_r = tid >> 3, pa_c = tid & 7;

    const int arow  = warp_m + (quad & 1) * 8 + lrow;
    const int ac_hi = quad >> 1;
    const int brow0 = warp_n + ((quad >> 1) & 1) * 8 + lrow;
    const int bc_lo = quad & 1;

    float c[NT8][4];
    #pragma unroll
    for (int ni = 0; ni < NT8; ni++)
        #pragma unroll
        for (int j = 0; j < 4; j++)
            c[ni][j] = 0.0f;

    float4 aR[2][2];

    auto ldgA = [&](int t) {
        const int kk = t * BK;
        #pragma unroll
        for (int i = 0; i < 2; i++) {
            int hc = tid + i * 256;          // half-chunk 0..511
            int r = hc >> 3, c8 = hc & 7;
            int grow = rowbase + r;
            if (grow < M) {
                const float4* src = reinterpret_cast<const float4*>(
                    A + (size_t)grow * KD + kk + c8 * 8);
                aR[i][0] = src[0];
                aR[i][1] = src[1];
            } else {
                aR[i][0] = make_float4(0.f, 0.f, 0.f, 0.f);
                aR[i][1] = make_float4(0.f, 0.f, 0.f, 0.f);
            }
        }
    };

    auto storeA = [&](int t) {
        char* st = smem + (t & 1) * STAGE;
        #pragma unroll
        for (int i = 0; i < 2; i++) {
            int hc = tid + i * 256;
            int r = hc >> 3, c8 = hc & 7;
            __half2 h0 = __float22half2_rn(make_float2(aR[i][0].x, aR[i][0].y));
            __half2 h1 = __float22half2_rn(make_float2(aR[i][0].z, aR[i][0].w));
            __half2 h2 = __float22half2_rn(make_float2(aR[i][1].x, aR[i][1].y));
            __half2 h3 = __float22half2_rn(make_float2(aR[i][1].z, aR[i][1].w));
            uint4 v;
            v.x = *reinterpret_cast<uint32_t*>(&h0);
            v.y = *reinterpret_cast<uint32_t*>(&h1);
            v.z = *reinterpret_cast<uint32_t*>(&h2);
            v.w = *reinterpret_cast<uint32_t*>(&h3);
            *reinterpret_cast<uint4*>(
                st + r * 128 + ((c8 ^ (r & 7)) << 4)) = v;
        }
    };

    auto issueB = [&](int t) {
        const int kk = t * BK;
        const uint32_t st = sbase + (t & 1) * STAGE;
        #pragma unroll
        for (int i = 0; i < 10; i++) {       // 320 rows x 8 chunks / 256 thr
            int r = pa_r + i * 32;
            const __half* src =
                Bt + (size_t)r * KD + kk + pa_c * 8;
            uint32_t dst = st + ABY + r * 128 + ((pa_c ^ (r & 7)) << 4);
            cp_async16(dst, src, 16u);
        }
        CP_COMMIT();
    };

    ldgA(0);
    issueB(0);
    issueB(1);
    storeA(0);
    CP_WAIT(1);
    __syncthreads();

    for (int t = 0; t < NST; t++) {
        const uint32_t st = sbase + (t & 1) * STAGE;
        if (t + 1 < NST) ldgA(t + 1);

        #pragma unroll
        for (int ks8 = 0; ks8 < BK / 8; ks8 += 2) {
            uint32_t af[4];
            {
                int cch = ks8 + ac_hi;
                uint32_t addr = st + arow * 128 + ((cch ^ (arow & 7)) << 4);
                LDSM_X4(af[0], af[1], af[2], af[3], addr);
            }
            #pragma unroll
            for (int nt = 0; nt < NT16; nt++) {
                uint32_t bf[4];
                int r = brow0 + nt * 16;
                int cch = ks8 + bc_lo;
                uint32_t addr = st + ABY + r * 128 + ((cch ^ (r & 7)) << 4);
                LDSM_X4(bf[0], bf[1], bf[2], bf[3], addr);
                MMA_F16(c[nt * 2 + 0], af, bf[0], bf[1]);
                MMA_F16(c[nt * 2 + 1], af, bf[2], bf[3]);
            }
        }
        __syncthreads();
        if (t + 1 < NST) {
            storeA(t + 1);
            if (t + 2 < NST) { issueB(t + 2); CP_WAIT(1); }
            else             { CP_WAIT(0); }
            __syncthreads();
        }
    }

    // ---- epilogue: bias + leaky, half outputs, per-tile column routing ----
    #pragma unroll
    for (int ni = 0; ni < NT8; ni++) {
        const int col = warp_n + ni * 8 + 2 * l;
        const bool isInit = (col >= 256);
        const float b0 = isInit ? bias1[col - 256] : bias0[col];
        const float b1 = isInit ? bias1[col - 255] : bias0[col + 1];
        #pragma unroll
        for (int hm = 0; hm < 2; hm++) {
            const int r = rowbase + warp_m + g + hm * 8;
            if (r >= M) continue;
            float ox = leaky(c[ni][hm * 2 + 0] + b0);
            float oy = leaky(c[ni][hm * 2 + 1] + b1);
            __half2 h = __float22half2_rn(make_float2(ox, oy));
            if (isInit)
                *reinterpret_cast<uint32_t*>(
                    a0h + (size_t)r * 64 + col - 256) =
                    *reinterpret_cast<uint32_t*>(&h);
            else
                *reinterpret_cast<uint32_t*>(
                    resh + (size_t)r * 256 + col) =
                    *reinterpret_cast<uint32_t*>(&h);
        }
    }
}

// ---------------------------------------------------------------------------
// FINAL GEMM: out = leaky(a2h @ wfT^T + b_fin) + resh.  128x128, fp32 out.
// ---------------------------------------------------------------------------
__global__ __launch_bounds__(256, 2)
void hgemm_fin(const __half* __restrict__ A, const __half* __restrict__ Bt,
               const float* __restrict__ bias, const __half* __restrict__ resh,
               float* __restrict__ C, int M)
{
    constexpr int KD    = 256;
    constexpr int BK    = 64;
    constexpr int NST   = KD / BK;
    constexpr int CTAN  = 128;
    constexpr int ABY   = 128 * 128;
    constexpr int BBY   = CTAN * 128;
    constexpr int STAGE = ABY + BBY;
    constexpr int NT16  = CTAN / 32;         // 4
    constexpr int NT8   = 2 * NT16;          // 8

    extern __shared__ char smem[];
    const uint32_t sbase = (uint32_t)__cvta_generic_to_shared(smem);

    const int tid  = threadIdx.x;
    const int wid  = tid >> 5;
    const int lane = tid & 31;
    const int g = lane >> 2;
    const int l = lane & 3;
    const int quad = lane >> 3;
    const int lrow = lane & 7;
    const int warp_m = (wid & 3) * 32;
    const int warp_n = (wid >> 2) * (CTAN / 2);
    const int rowbase = blockIdx.x * 128;
    const int colbase = blockIdx.y * CTAN;

    const int pa_r = tid >> 3, pa_c = tid & 7;
    const int arow  = warp_m + (quad & 1) * 8 + lrow;
    const int ac_hi = quad >> 1;
    const int brow0 = warp_n + ((quad >> 1) & 1) * 8 + lrow;
    const int bc_lo = quad & 1;

    float c[2][NT8][4];
    #pragma unroll
    for (int mi = 0; mi < 2; mi++)
        #pragma unroll
        for (int ni = 0; ni < NT8; ni++)
            #pragma unroll
            for (int j = 0; j < 4; j++)
                c[mi][ni][j] = 0.0f;

    auto issue = [&](int t) {
        const int kk = t * BK;
        const uint32_t st = sbase + (t & 1) * STAGE;
        #pragma unroll
        for (int i = 0; i < 4; i++) {
            int r = pa_r + i * 32;
            int grow = rowbase + r;
            bool v = grow < M;
            const __half* src =
                A + (size_t)(v ? grow : 0) * KD + kk + pa_c * 8;
            uint32_t dst = st + r * 128 + ((pa_c ^ (r & 7)) << 4);
            cp_async16(dst, src, v ? 16u : 0u);
        }
        #pragma unroll
        for (int i = 0; i < 4; i++) {
            int r = pa_r + i * 32;
            const __half* src =
                Bt + (size_t)(colbase + r) * KD + kk + pa_c * 8;
            uint32_t dst = st + ABY + r * 128 + ((pa_c ^ (r & 7)) << 4);
            cp_async16(dst, src, 16u);
        }
        CP_COMMIT();
    };

    issue(0);
    issue(1);
    CP_WAIT(1);
    __syncthreads();

    for (int t = 0; t < NST; t++) {
        const uint32_t st = sbase + (t & 1) * STAGE;
        #pragma unroll
        for (int ks8 = 0; ks8 < BK / 8; ks8 += 2) {
            uint32_t af[2][4];
            #pragma unroll
            for (int mi = 0; mi < 2; mi++) {
                int r = arow + mi * 16;
                int cch = ks8 + ac_hi;
                uint32_t addr = st + r * 128 + ((cch ^ (r & 7)) << 4);
                LDSM_X4(af[mi][0], af[mi][1], af[mi][2], af[mi][3], addr);
            }
            #pragma unroll
            for (int nt = 0; nt < NT16; nt++) {
                uint32_t bf[4];
                int r = brow0 + nt * 16;
                int cch = ks8 + bc_lo;
                uint32_t addr = st + ABY + r * 128 + ((cch ^ (r & 7)) << 4);
                LDSM_X4(bf[0], bf[1], bf[2], bf[3], addr);
                MMA_F16(c[0][nt * 2 + 0], af[0], bf[0], bf[1]);
                MMA_F16(c[1][nt * 2 + 0], af[1], bf[0], bf[1]);
                MMA_F16(c[0][nt * 2 + 1], af[0], bf[2], bf[3]);
                MMA_F16(c[1][nt * 2 + 1], af[1], bf[2], bf[3]);
            }
        }
        __syncthreads();
        if (t + 1 < NST) {
            if (t + 2 < NST) { issue(t + 2); CP_WAIT(1); }
            else             { CP_WAIT(0); }
            __syncthreads();
        }
    }

    #pragma unroll
    for (int mi = 0; mi < 2; mi++) {
        #pragma unroll
        for (int ni = 0; ni < NT8; ni++) {
            const int col = colbase + warp_n + ni * 8 + 2 * l;
            const float b0 = bias[col];
            const float b1 = bias[col + 1];
            #pragma unroll
            for (int hm = 0; hm < 2; hm++) {
                const int r = rowbase + warp_m + mi * 16 + g + hm * 8;
                if (r >= M) continue;
                uint32_t ru = *reinterpret_cast<const uint32_t*>(
                    resh + (size_t)r * 256 + col);
                float2 rv = __half22float2(u2h2(ru));
                float2 o;
                o.x = leaky(c[mi][ni][hm * 2 + 0] + b0) + rv.x;
                o.y = leaky(c[mi][ni][hm * 2 + 1] + b1) + rv.y;
                *reinterpret_cast<float2*>(C + (size_t)r * 256 + col) = o;
            }
        }
    }
}

// ---------------------------------------------------------------------------
// gather1: a1h[p, 64:128] = mean_k a0h[idx[p,k], 0:64]
// 4 points per warp, 8 lanes/point, uint4 loads, pairwise HADD2 pre-reduce.
// ---------------------------------------------------------------------------
__global__ __launch_bounds__(256)
void gather1(const __half* __restrict__ a0h, const int* __restrict__ idx,
             __half* __restrict__ a1h, int N)
{
    __shared__ int is[32][16];
    const int tid  = threadIdx.x;
    const int wid  = tid >> 5;
    const int lane = tid & 31;
    const int pbase = blockIdx.x * 32;

    #pragma unroll
    for (int i = 0; i < 2; i++) {
        int e = tid + i * 256;
        int pp = pbase + (e >> 4);
        is[e >> 4][e & 15] = (pp < N) ? idx[(size_t)pp * 16 + (e & 15)] : 0;
    }
    __syncthreads();

    const int pl = wid * 4 + (lane >> 3);   // local point 0..31
    const int sl = lane & 7;
    const int p  = pbase + pl;
    if (p >= N) return;

    const uint4* src = reinterpret_cast<const uint4*>(a0h);  // 8 uint4/row
    float s[8];
    #pragma unroll
    for (int i = 0; i < 8; i++) s[i] = 0.f;

    #pragma unroll
    for (int k = 0; k < 16; k += 2) {
        uint4 ua = src[(size_t)is[pl][k]     * 8 + sl];
        uint4 ub = src[(size_t)is[pl][k + 1] * 8 + sl];
        __half2 h0 = __hadd2(u2h2(ua.x), u2h2(ub.x));
        __half2 h1 = __hadd2(u2h2(ua.y), u2h2(ub.y));
        __half2 h2 = __hadd2(u2h2(ua.z), u2h2(ub.z));
        __half2 h3 = __hadd2(u2h2(ua.w), u2h2(ub.w));
        float2 f0 = __half22float2(h0);
        float2 f1 = __half22float2(h1);
        float2 f2 = __half22float2(h2);
        float2 f3 = __half22float2(h3);
        s[0] += f0.x; s[1] += f0.y; s[2] += f1.x; s[3] += f1.y;
        s[4] += f2.x; s[5] += f2.y; s[6] += f3.x; s[7] += f3.y;
    }

    __half2 o0 = __float22half2_rn(make_float2(s[0] * 0.0625f, s[1] * 0.0625f));
    __half2 o1 = __float22half2_rn(make_float2(s[2] * 0.0625f, s[3] * 0.0625f));
    __half2 o2 = __float22half2_rn(make_float2(s[4] * 0.0625f, s[5] * 0.0625f));
    __half2 o3 = __float22half2_rn(make_float2(s[6] * 0.0625f, s[7] * 0.0625f));
    uint4 o;
    o.x = *reinterpret_cast<uint32_t*>(&o0);
    o.y = *reinterpret_cast<uint32_t*>(&o1);
    o.z = *reinterpret_cast<uint32_t*>(&o2);
    o.w = *reinterpret_cast<uint32_t*>(&o3);
    *reinterpret_cast<uint4*>(a1h + (size_t)p * 128 + 64 + sl * 8) = o;
}

// ---------------------------------------------------------------------------
// gather2: a2h[p, 128:256] = mean_k a1h[idx[p,k], 0:128]
// 2 points per warp, 16 lanes/point, uint4 loads, pairwise HADD2 pre-reduce.
// ---------------------------------------------------------------------------
__global__ __launch_bounds__(256)
void gather2(const __half* __restrict__ a1h, const int* __restrict__ idx,
             __half* __restrict__ a2h, int N)
{
    __shared__ int is[16][16];
    const int tid  = threadIdx.x;
    const int wid  = tid >> 5;
    const int lane = tid & 31;
    const int pbase = blockIdx.x * 16;

    {
        int pp = pbase + (tid >> 4);
        is[tid >> 4][tid & 15] =
            (pp < N) ? idx[(size_t)pp * 16 + (tid & 15)] : 0;
    }
    __syncthreads();

    const int pl = wid * 2 + (lane >> 4);
    const int sl = lane & 15;
    const int p  = pbase + pl;
    if (p >= N) return;

    const uint4* src = reinterpret_cast<const uint4*>(a1h);  // 16 uint4/row
    float s[8];
    #pragma unroll
    for (int i = 0; i < 8; i++) s[i] = 0.f;

    #pragma unroll
    for (int k = 0; k < 16; k += 2) {
        uint4 ua = src[(size_t)is[pl][k]     * 16 + sl];
        uint4 ub = src[(size_t)is[pl][k + 1] * 16 + sl];
        __half2 h0 = __hadd2(u2h2(ua.x), u2h2(ub.x));
        __half2 h1 = __hadd2(u2h2(ua.y), u2h2(ub.y));
        __half2 h2 = __hadd2(u2h2(ua.z), u2h2(ub.z));
        __half2 h3 = __hadd2(u2h2(ua.w), u2h2(ub.w));
        float2 f0 = __half22float2(h0);
        float2 f1 = __half22float2(h1);
        float2 f2 = __half22float2(h2);
        float2 f3 = __half22float2(h3);
        s[0] += f0.x; s[1] += f0.y; s[2] += f1.x; s[3] += f1.y;
        s[4] += f2.x; s[5] += f2.y; s[6] += f3.x; s[7] += f3.y;
    }

    __half2 o0 = __float22half2_rn(make_float2(s[0] * 0.0625f, s[1] * 0.0625f));
    __half2 o1 = __float22half2_rn(make_float2(s[2] * 0.0625f, s[3] * 0.0625f));
    __half2 o2 = __float22half2_rn(make_float2(s[4] * 0.0625f, s[5] * 0.0625f));
    __half2 o3 = __float22half2_rn(make_float2(s[6] * 0.0625f, s[7] * 0.0625f));
    uint4 o;
    o.x = *reinterpret_cast<uint32_t*>(&o0);
    o.y = *reinterpret_cast<uint32_t*>(&o1);
    o.z = *reinterpret_cast<uint32_t*>(&o2);
    o.w = *reinterpret_cast<uint32_t*>(&o3);
    *reinterpret_cast<uint4*>(a2h + (size_t)p * 256 + 128 + sl * 8) = o;
}

// ---------------------------------------------------------------------------
extern "C" void kernel_launch(void* const* d_in, const int* in_sizes, int n_in,
                              void* d_out, int out_size)
{
    const float* X      = (const float*)d_in[0];
    const float* geom   = (const float*)d_in[1];
    const int*   idx    = (const int*)  d_in[2];
    const float* w_res  = (const float*)d_in[3];
    const float* b_res  = (const float*)d_in[4];
    const float* w_init = (const float*)d_in[5];
    const float* b_init = (const float*)d_in[6];
    const float* w_g1   = (const float*)d_in[7];
    const float* b_g1   = (const float*)d_in[8];
    const float* w_g2   = (const float*)d_in[9];
    const float* b_g2   = (const float*)d_in[10];
    const float* w_fin  = (const float*)d_in[11];
    const float* b_fin  = (const float*)d_in[12];
    float* out = (float*)d_out;

    const int N = in_sizes[0] / DIM;

    __half *resh, *a0h, *a1h, *a2h, *wcat, *wfT;
    cudaGetSymbolAddress((void**)&resh, g_resh);
    cudaGetSymbolAddress((void**)&a0h,  g_a0h);
    cudaGetSymbolAddress((void**)&a1h,  g_a1h);
    cudaGetSymbolAddress((void**)&a2h,  g_a2h);
    cudaGetSymbolAddress((void**)&wcat, g_wcat);
    cudaGetSymbolAddress((void**)&wfT,  g_wfT);

    constexpr int SMEM_CAT   = 2 * (64 * 128 + 320 * 128);   // 96 KB
    constexpr int SMEM_FINAL = 2 * (128 * 128 + 128 * 128);  // 64 KB
    cudaFuncSetAttribute(hgemm_cat,
                         cudaFuncAttributeMaxDynamicSharedMemorySize, SMEM_CAT);
    cudaFuncSetAttribute(hgemm_fin,
                         cudaFuncAttributeMaxDynamicSharedMemorySize, SMEM_FINAL);

    const int gridP  = (N + 7) / 8;

    // 0) weight prep + geometry MLP (one launch)
    prep_geom<<<144 + gridP, 256>>>(w_res, w_init, w_fin, wcat, wfT,
                                    geom, w_g1, b_g1, w_g2, b_g2,
                                    a1h, a2h, N);
    // 1+2) fused: resh (half) + a0h (half) = leaky(X @ [w_res|w_init] + b)
    hgemm_cat<<<dim3((N + 63) / 64, 1), 256, SMEM_CAT>>>(
        X, wcat, b_res, b_init, resh, a0h, N);
    // 3) gather half of LFA1
    gather1<<<(N + 31) / 32, 256>>>(a0h, idx, a1h, N);
    // 4) gather half of LFA2
    gather2<<<(N + 15) / 16, 256>>>(a1h, idx, a2h, N);
    // 5) out = leaky(a2 @ w_fin + b_fin) + resh
    hgemm_fin<<<dim3((N + 127) / 128, 2), 256, SMEM_FINAL>>>(
        a2h, wfT, b_fin, resh, out, N);
}